// round 10
// baseline (speedup 1.0000x reference)
#include <cuda_runtime.h>
#include <cstdint>

// FocusModules, one-shot TMA, 2 windows per CTA (512 thr), 3 CTAs/SM.
// x: [N, 256] f32.  out (float32): [ mask1 (N) | compressed (N*256) ].
//
// One CTA per 64 tokens (4096 CTAs). Tile rows 0..64 = tokens t0-1..t0+63.
// Warp w (0..15) owns tokens t0+4w..t0+4w+3 (tile rows 4w+1..4w+4).
// Warps 0-7 belong to window 0, warps 8-15 to window 1.
// mean_sim[i] = inv_i * dot(raw_i, s_win)/32, s_win[c] = sum_r raw[r][c]*inv_r.

#define WTOK 32

struct __align__(128) Smem {
    float tile[65 * 256];        // 65 KB
    float s_s[2][256];           // weighted column sums, one per window
    float inv_s[65];             // per-row 1/||x||
    float ms_s[64];              // per-token mean similarity
    unsigned long long mbar;
};

__device__ __forceinline__ uint32_t smem_u32(const void* p) {
    return (uint32_t)__cvta_generic_to_shared(p);
}
__device__ __forceinline__ float warp_sum(float v) {
    #pragma unroll
    for (int o = 16; o; o >>= 1) v += __shfl_xor_sync(0xFFFFFFFFu, v, o);
    return v;
}
__device__ __forceinline__ float dot4(float4 a, float4 b) {
    return a.x * b.x + a.y * b.y + a.z * b.z + a.w * b.w;
}

__global__ void __launch_bounds__(512, 3)
focus_kernel(const float* __restrict__ x,
             float* __restrict__ mask_out,        // N floats (0/1)
             float* __restrict__ comp_out)        // N*256 floats
{
    extern __shared__ __align__(128) char smem_raw[];
    Smem* sm = reinterpret_cast<Smem*>(smem_raw);

    const int w     = blockIdx.x;
    const int warp  = threadIdx.x >> 5;   // 0..15
    const int lane  = threadIdx.x & 31;
    const int t0    = w * 64;             // first global token of this CTA
    const int rbase = 4 * warp;           // warp reads rows rbase..rbase+4

    // ---- Bulk load rows t0-1 .. t0+63 (w=0: t0..t0+63 into tile+1KB) ----
    const uint32_t mb = smem_u32(&sm->mbar);
    if (threadIdx.x == 0) {
        asm volatile("mbarrier.init.shared::cta.b64 [%0], %1;" :: "r"(mb), "r"(1) : "memory");
        asm volatile("fence.proxy.async.shared::cta;" ::: "memory");
        const uint32_t bytes = (w ? 65u : 64u) * 1024u;
        const float*   src   = x + (size_t)(w ? (t0 - 1) : 0) * 256;
        const uint32_t dst   = smem_u32(sm->tile) + (w ? 0u : 1024u);
        asm volatile("mbarrier.arrive.expect_tx.shared::cta.b64 _, [%0], %1;"
                     :: "r"(mb), "r"(bytes) : "memory");
        asm volatile("cp.async.bulk.shared::cta.global.mbarrier::complete_tx::bytes [%0], [%1], %2, [%3];"
                     :: "r"(dst), "l"(src), "r"(bytes), "r"(mb) : "memory");
    }
    __syncthreads();
    asm volatile(
        "{\n\t.reg .pred P;\n\t"
        "W%=:\n\t"
        "mbarrier.try_wait.parity.acquire.cta.shared::cta.b64 P, [%0], 0;\n\t"
        "@P bra D%=;\n\t"
        "bra W%=;\n\t"
        "D%=:\n\t}"
        :: "r"(mb) : "memory");

    float4* t4 = (float4*)sm->tile;
    if (w == 0 && warp == 0) {           // deterministic row 0 for the first CTA
        const float4 z = make_float4(0.f, 0.f, 0.f, 0.f);
        t4[lane] = z;  t4[32 + lane] = z;
        __syncwarp();                    // warp 0 reads row 0 right below
    }

    // ---- Phase 1: one rolling pass -> norms (5 rows) + adjacent raw dots (4) ----
    float da[4];
    {
        float nrm[5];
        float4 plo, phi;
        #pragma unroll
        for (int i = 0; i < 5; i++) {
            const float4 lo = t4[(rbase + i) * 64 + lane];
            const float4 hi = t4[(rbase + i) * 64 + 32 + lane];
            nrm[i] = dot4(lo, lo) + dot4(hi, hi);
            if (i > 0) da[i - 1] = dot4(lo, plo) + dot4(hi, phi);
            plo = lo;  phi = hi;
        }
        #pragma unroll
        for (int o = 16; o; o >>= 1) {
            #pragma unroll
            for (int i = 0; i < 5; i++) nrm[i] += __shfl_xor_sync(0xFFFFFFFFu, nrm[i], o);
            #pragma unroll
            for (int i = 0; i < 4; i++) da[i]  += __shfl_xor_sync(0xFFFFFFFFu, da[i],  o);
        }
        if (lane == 0) {
            #pragma unroll
            for (int i = 1; i < 5; i++)
                sm->inv_s[rbase + i] = 1.0f / fmaxf(sqrtf(nrm[i]), 1e-12f);
            if (warp == 0)
                sm->inv_s[0] = 1.0f / fmaxf(sqrtf(nrm[0]), 1e-12f);
        }
    }
    __syncthreads();

    // ---- Phase 2: weighted column sums, both windows concurrently ----
    {
        const int win = threadIdx.x >> 8;          // 0 or 1
        const int c   = threadIdx.x & 255;
        const int rs  = 1 + win * WTOK;            // rows rs..rs+31
        float acc = 0.0f;
        #pragma unroll
        for (int r = 0; r < WTOK; r++)
            acc += sm->tile[(rs + r) * 256 + c] * sm->inv_s[rs + r];
        sm->s_s[win][c] = acc;
    }
    __syncthreads();

    // ---- Phase 3: mean-sim dots + zero masked rows + per-warp early store ----
    {
        const int win = warp >> 3;                 // this warp's window
        const float4* sv = (const float4*)sm->s_s[win];
        const float4 s0 = sv[lane], s1 = sv[32 + lane];
        const float4 z  = make_float4(0.f, 0.f, 0.f, 0.f);
        float dms[4];
        #pragma unroll
        for (int i = 0; i < 4; i++) {
            const int r = rbase + 1 + i;
            const float4 lo = t4[r * 64 + lane];
            const float4 hi = t4[r * 64 + 32 + lane];
            dms[i] = dot4(lo, s0) + dot4(hi, s1);
        }
        #pragma unroll
        for (int o = 16; o; o >>= 1) {
            #pragma unroll
            for (int i = 0; i < 4; i++) dms[i] += __shfl_xor_sync(0xFFFFFFFFu, dms[i], o);
        }
        #pragma unroll
        for (int i = 0; i < 4; i++) {
            const int r = rbase + 1 + i;
            const bool m3 = ((t0 + 4 * warp + i) == 0) ||
                            (sm->inv_s[r] * sm->inv_s[r - 1] * da[i] < 0.7f);
            if (!m3) { t4[r * 64 + lane] = z;  t4[r * 64 + 32 + lane] = z; }
        }
        if (lane == 0) {
            #pragma unroll
            for (int i = 0; i < 4; i++)
                sm->ms_s[4 * warp + i] = sm->inv_s[rbase + 1 + i] * dms[i] * (1.0f / 32.0f);
        }
        // this warp's 4 rows are final -> 4 KB bulk store now
        __syncwarp();
        if (lane == 0) {
            asm volatile("fence.proxy.async.shared::cta;" ::: "memory");
            asm volatile("cp.async.bulk.global.shared::cta.bulk_group [%0], [%1], %2;"
                         :: "l"(comp_out + (size_t)(t0 + 4 * warp) * 256),
                            "r"(smem_u32(sm->tile) + (uint32_t)(rbase + 1) * 1024u),
                            "r"(4096u) : "memory");
            asm volatile("cp.async.bulk.commit_group;" ::: "memory");
        }
    }
    __syncthreads();

    // ---- Phase 4: window statistics (warp 0 -> window 0, warp 8 -> window 1) ----
    if ((warp & 7) == 0) {
        const int win = warp >> 3;
        const float m = sm->ms_s[win * WTOK + lane];
        float mu = warp_sum(m) * (1.0f / 32.0f);
        float d = m - mu;
        float var = warp_sum(d * d) * (1.0f / 31.0f);   // ddof=1
        float sd = sqrtf(var);
        bool keep = !(m > mu + sd);
        unsigned bal = __ballot_sync(0xFFFFFFFFu, keep);
        if (bal == 0u) {
            // fallback: keep argmin(mean_sim), first index on ties
            float bv = m; int bi = lane;
            #pragma unroll
            for (int o = 16; o; o >>= 1) {
                float ov = __shfl_xor_sync(0xFFFFFFFFu, bv, o);
                int   oi = __shfl_xor_sync(0xFFFFFFFFu, bi, o);
                if (ov < bv || (ov == bv && oi < bi)) { bv = ov; bi = oi; }
            }
            keep = (lane == bi);
        }
        mask_out[t0 + win * WTOK + lane] = keep ? 1.0f : 0.0f;
    }

    // drain this warp's bulk store before the CTA retires (smem reuse safety)
    if (lane == 0) {
        asm volatile("cp.async.bulk.wait_group 0;" ::: "memory");
    }
}

extern "C" void kernel_launch(void* const* d_in, const int* in_sizes, int n_in,
                              void* d_out, int out_size)
{
    const float* x = (const float*)d_in[0];
    const int N = in_sizes[0] / 256;       // tokens
    const int ncta = N / 64;               // 2 windows per CTA

    float* out = (float*)d_out;
    float* mask_out = out;                 // first N floats
    float* comp_out = out + N;             // N*256 floats

    cudaFuncSetAttribute(focus_kernel,
                         cudaFuncAttributeMaxDynamicSharedMemorySize,
                         (int)sizeof(Smem));
    focus_kernel<<<ncta, 512, sizeof(Smem)>>>(x, mask_out, comp_out);
}

// round 11
// speedup vs baseline: 1.0026x; 1.0026x over previous
#include <cuda_runtime.h>
#include <cstdint>

// FocusModules: TMA bulk load + register-direct STG stores.
// x: [N, 256] f32.  out (float32): [ mask1 (N) | compressed (N*256) ].
//
// One CTA (256 thr, 8 warps) per 32-token window (8192 CTAs), 6 CTAs/SM.
// Tile rows 0..32 = tokens t0-1..t0+31.  Warp w owns tokens 4w..4w+3.
// mean_sim[i] = inv_i * dot(raw_i, s)/32, s[c] = sum_r raw[r][c]*inv_r.
// Epilogue stores masked rows straight from registers (no smem zeroing,
// no TMA-store smem re-read, no bulk-group drain).

#define WTOK 32

struct __align__(128) Smem {
    float tile[33 * 256];        // 33 KB
    float s_s[256];              // weighted column sums
    float inv_s[33];             // per-row 1/||x||
    float ms_s[WTOK];            // per-token mean similarity
    unsigned long long mbar;
};

__device__ __forceinline__ uint32_t smem_u32(const void* p) {
    return (uint32_t)__cvta_generic_to_shared(p);
}
__device__ __forceinline__ float warp_sum(float v) {
    #pragma unroll
    for (int o = 16; o; o >>= 1) v += __shfl_xor_sync(0xFFFFFFFFu, v, o);
    return v;
}
__device__ __forceinline__ float dot4(float4 a, float4 b) {
    return a.x * b.x + a.y * b.y + a.z * b.z + a.w * b.w;
}

__global__ void __launch_bounds__(256, 6)
focus_kernel(const float* __restrict__ x,
             float* __restrict__ mask_out,        // N floats (0/1)
             float* __restrict__ comp_out)        // N*256 floats
{
    extern __shared__ __align__(128) char smem_raw[];
    Smem* sm = reinterpret_cast<Smem*>(smem_raw);

    const int w     = blockIdx.x;
    const int warp  = threadIdx.x >> 5;   // 0..7, owns tokens 4w..4w+3
    const int lane  = threadIdx.x & 31;
    const int t0    = w * WTOK;
    const int rbase = 4 * warp;           // warp reads rows rbase..rbase+4

    // ---- Bulk load rows t0-1 .. t0+31 (w=0: rows t0..t0+31 into tile+1KB) ----
    const uint32_t mb = smem_u32(&sm->mbar);
    if (threadIdx.x == 0) {
        asm volatile("mbarrier.init.shared::cta.b64 [%0], %1;" :: "r"(mb), "r"(1) : "memory");
        asm volatile("fence.proxy.async.shared::cta;" ::: "memory");
        const uint32_t bytes = (w ? 33u : 32u) * 1024u;
        const float*   src   = x + (size_t)(w ? (t0 - 1) : 0) * 256;
        const uint32_t dst   = smem_u32(sm->tile) + (w ? 0u : 1024u);
        asm volatile("mbarrier.arrive.expect_tx.shared::cta.b64 _, [%0], %1;"
                     :: "r"(mb), "r"(bytes) : "memory");
        asm volatile("cp.async.bulk.shared::cta.global.mbarrier::complete_tx::bytes [%0], [%1], %2, [%3];"
                     :: "r"(dst), "l"(src), "r"(bytes), "r"(mb) : "memory");
    }
    __syncthreads();
    asm volatile(
        "{\n\t.reg .pred P;\n\t"
        "W%=:\n\t"
        "mbarrier.try_wait.parity.acquire.cta.shared::cta.b64 P, [%0], 0;\n\t"
        "@P bra D%=;\n\t"
        "bra W%=;\n\t"
        "D%=:\n\t}"
        :: "r"(mb) : "memory");

    float4* t4 = (float4*)sm->tile;
    if (w == 0 && warp == 0) {           // deterministic row 0 for window 0
        const float4 z = make_float4(0.f, 0.f, 0.f, 0.f);
        t4[lane] = z;  t4[32 + lane] = z;
        __syncwarp();                    // warp 0 reads row 0 right below
    }

    // ---- Phase 1: one rolling pass -> norms (5 rows) + adjacent raw dots (4) ----
    float da[4];
    {
        float nrm[5];
        float4 plo, phi;
        #pragma unroll
        for (int i = 0; i < 5; i++) {
            const float4 lo = t4[(rbase + i) * 64 + lane];
            const float4 hi = t4[(rbase + i) * 64 + 32 + lane];
            nrm[i] = dot4(lo, lo) + dot4(hi, hi);
            if (i > 0) da[i - 1] = dot4(lo, plo) + dot4(hi, phi);
            plo = lo;  phi = hi;
        }
        #pragma unroll
        for (int o = 16; o; o >>= 1) {
            #pragma unroll
            for (int i = 0; i < 5; i++) nrm[i] += __shfl_xor_sync(0xFFFFFFFFu, nrm[i], o);
            #pragma unroll
            for (int i = 0; i < 4; i++) da[i]  += __shfl_xor_sync(0xFFFFFFFFu, da[i],  o);
        }
        if (lane == 0) {
            #pragma unroll
            for (int i = 1; i < 5; i++)
                sm->inv_s[rbase + i] = 1.0f / fmaxf(sqrtf(nrm[i]), 1e-12f);
            if (warp == 0)
                sm->inv_s[0] = 1.0f / fmaxf(sqrtf(nrm[0]), 1e-12f);
        }
    }
    __syncthreads();

    // ---- Phase 2: weighted column sums (deterministic order) ----
    {
        const int c = threadIdx.x;        // 256 threads, one column each
        float acc = 0.0f;
        #pragma unroll
        for (int r = 1; r <= WTOK; r++) acc += sm->tile[r * 256 + c] * sm->inv_s[r];
        sm->s_s[c] = acc;
    }
    __syncthreads();

    // ---- Phase 3: mean-sim dots + masked stores straight from registers ----
    {
        const float4* sv = (const float4*)sm->s_s;
        const float4 s0 = sv[lane], s1 = sv[32 + lane];
        const float4 z  = make_float4(0.f, 0.f, 0.f, 0.f);
        float4* dst = (float4*)(comp_out + (size_t)(t0 + 4 * warp) * 256);
        float dms[4];
        #pragma unroll
        for (int i = 0; i < 4; i++) {
            const int r = rbase + 1 + i;
            const float4 lo = t4[r * 64 + lane];
            const float4 hi = t4[r * 64 + 32 + lane];
            dms[i] = dot4(lo, s0) + dot4(hi, s1);
            const bool m3 = ((t0 + 4 * warp + i) == 0) ||
                            (sm->inv_s[r] * sm->inv_s[r - 1] * da[i] < 0.7f);
            __stcs(dst + i * 64 + lane,      m3 ? lo : z);
            __stcs(dst + i * 64 + 32 + lane, m3 ? hi : z);
        }
        #pragma unroll
        for (int o = 16; o; o >>= 1) {
            #pragma unroll
            for (int i = 0; i < 4; i++) dms[i] += __shfl_xor_sync(0xFFFFFFFFu, dms[i], o);
        }
        if (lane == 0) {
            #pragma unroll
            for (int i = 0; i < 4; i++)
                sm->ms_s[4 * warp + i] = sm->inv_s[rbase + 1 + i] * dms[i] * (1.0f / 32.0f);
        }
    }
    __syncthreads();

    // ---- Phase 4: window statistics (warp 0) ----
    if (warp == 0) {
        const float m = sm->ms_s[lane];
        float mu = warp_sum(m) * (1.0f / 32.0f);
        float d = m - mu;
        float var = warp_sum(d * d) * (1.0f / 31.0f);   // ddof=1
        float sd = sqrtf(var);
        bool keep = !(m > mu + sd);
        unsigned bal = __ballot_sync(0xFFFFFFFFu, keep);
        if (bal == 0u) {
            // fallback: keep argmin(mean_sim), first index on ties
            float bv = m; int bi = lane;
            #pragma unroll
            for (int o = 16; o; o >>= 1) {
                float ov = __shfl_xor_sync(0xFFFFFFFFu, bv, o);
                int   oi = __shfl_xor_sync(0xFFFFFFFFu, bi, o);
                if (ov < bv || (ov == bv && oi < bi)) { bv = ov; bi = oi; }
            }
            keep = (lane == bi);
        }
        mask_out[t0 + lane] = keep ? 1.0f : 0.0f;
    }
}

extern "C" void kernel_launch(void* const* d_in, const int* in_sizes, int n_in,
                              void* d_out, int out_size)
{
    const float* x = (const float*)d_in[0];
    const int N = in_sizes[0] / 256;       // tokens
    const int nwin = N / WTOK;             // windows

    float* out = (float*)d_out;
    float* mask_out = out;                 // first N floats
    float* comp_out = out + N;             // N*256 floats

    cudaFuncSetAttribute(focus_kernel,
                         cudaFuncAttributeMaxDynamicSharedMemorySize,
                         (int)sizeof(Smem));
    focus_kernel<<<nwin, 256, sizeof(Smem)>>>(x, mask_out, comp_out);
}

// round 12
// speedup vs baseline: 1.0209x; 1.0182x over previous
#include <cuda_runtime.h>
#include <cstdint>

// FocusModules, one-shot TMA per window, 256-thread CTAs, 6 CTAs/SM.
// x: [N, 256] f32.  out (float32): [ mask1 (N) | compressed (N*256) ].
//
// One CTA per 32-token window (8192 CTAs). Tile rows 0..32 = tokens t0-1..t0+31.
// mean_sim[i] = inv_i * dot(raw_i, s)/32, s[c] = sum_r raw[r][c]*inv_r.
// Rolling pass fuses norms + adjacent dots; per-warp early TMA stores.
// L2 evict_first on both streams; exit drain waits only for smem reads.

#define WTOK 32

struct __align__(128) Smem {
    float tile[33 * 256];        // 33 KB
    float s_s[256];              // weighted column sums
    float inv_s[33];             // per-row 1/||x||
    float ms_s[WTOK];            // per-token mean similarity
    unsigned long long mbar;
};

__device__ __forceinline__ uint32_t smem_u32(const void* p) {
    return (uint32_t)__cvta_generic_to_shared(p);
}
__device__ __forceinline__ float warp_sum(float v) {
    #pragma unroll
    for (int o = 16; o; o >>= 1) v += __shfl_xor_sync(0xFFFFFFFFu, v, o);
    return v;
}
__device__ __forceinline__ float dot4(float4 a, float4 b) {
    return a.x * b.x + a.y * b.y + a.z * b.z + a.w * b.w;
}

__global__ void __launch_bounds__(256, 6)
focus_kernel(const float* __restrict__ x,
             float* __restrict__ mask_out,        // N floats (0/1)
             float* __restrict__ comp_out)        // N*256 floats
{
    extern __shared__ __align__(128) char smem_raw[];
    Smem* sm = reinterpret_cast<Smem*>(smem_raw);

    const int w     = blockIdx.x;
    const int warp  = threadIdx.x >> 5;   // 0..7, owns tokens 4w..4w+3
    const int lane  = threadIdx.x & 31;
    const int t0    = w * WTOK;
    const int rbase = 4 * warp;           // warp reads rows rbase..rbase+4

    uint64_t pol;                         // streaming: evict_first in L2
    asm volatile("createpolicy.fractional.L2::evict_first.b64 %0;" : "=l"(pol));

    // ---- Bulk load rows t0-1 .. t0+31 (w=0: rows t0..t0+31 into tile+1KB) ----
    const uint32_t mb = smem_u32(&sm->mbar);
    if (threadIdx.x == 0) {
        asm volatile("mbarrier.init.shared::cta.b64 [%0], %1;" :: "r"(mb), "r"(1) : "memory");
        asm volatile("fence.proxy.async.shared::cta;" ::: "memory");
        const uint32_t bytes = (w ? 33u : 32u) * 1024u;
        const float*   src   = x + (size_t)(w ? (t0 - 1) : 0) * 256;
        const uint32_t dst   = smem_u32(sm->tile) + (w ? 0u : 1024u);
        asm volatile("mbarrier.arrive.expect_tx.shared::cta.b64 _, [%0], %1;"
                     :: "r"(mb), "r"(bytes) : "memory");
        asm volatile("cp.async.bulk.shared::cta.global.mbarrier::complete_tx::bytes.L2::cache_hint"
                     " [%0], [%1], %2, [%3], %4;"
                     :: "r"(dst), "l"(src), "r"(bytes), "r"(mb), "l"(pol) : "memory");
    }
    __syncthreads();
    asm volatile(
        "{\n\t.reg .pred P;\n\t"
        "W%=:\n\t"
        "mbarrier.try_wait.parity.acquire.cta.shared::cta.b64 P, [%0], 0;\n\t"
        "@P bra D%=;\n\t"
        "bra W%=;\n\t"
        "D%=:\n\t}"
        :: "r"(mb) : "memory");

    float4* t4 = (float4*)sm->tile;
    if (w == 0 && warp == 0) {           // deterministic row 0 for window 0
        const float4 z = make_float4(0.f, 0.f, 0.f, 0.f);
        t4[lane] = z;  t4[32 + lane] = z;
        __syncwarp();                    // warp 0 reads row 0 right below
    }

    // ---- Phase 1: one rolling pass -> norms (5 rows) + adjacent raw dots (4) ----
    float da[4];
    {
        float nrm[5];
        float4 plo, phi;
        #pragma unroll
        for (int i = 0; i < 5; i++) {
            const float4 lo = t4[(rbase + i) * 64 + lane];
            const float4 hi = t4[(rbase + i) * 64 + 32 + lane];
            nrm[i] = dot4(lo, lo) + dot4(hi, hi);
            if (i > 0) da[i - 1] = dot4(lo, plo) + dot4(hi, phi);
            plo = lo;  phi = hi;
        }
        #pragma unroll
        for (int o = 16; o; o >>= 1) {
            #pragma unroll
            for (int i = 0; i < 5; i++) nrm[i] += __shfl_xor_sync(0xFFFFFFFFu, nrm[i], o);
            #pragma unroll
            for (int i = 0; i < 4; i++) da[i]  += __shfl_xor_sync(0xFFFFFFFFu, da[i],  o);
        }
        if (lane == 0) {
            #pragma unroll
            for (int i = 1; i < 5; i++)
                sm->inv_s[rbase + i] = 1.0f / fmaxf(sqrtf(nrm[i]), 1e-12f);
            if (warp == 0)
                sm->inv_s[0] = 1.0f / fmaxf(sqrtf(nrm[0]), 1e-12f);
        }
    }
    __syncthreads();

    // ---- Phase 2: weighted column sums (deterministic order) ----
    {
        const int c = threadIdx.x;        // 256 threads, one column each
        float acc = 0.0f;
        #pragma unroll
        for (int r = 1; r <= WTOK; r++) acc += sm->tile[r * 256 + c] * sm->inv_s[r];
        sm->s_s[c] = acc;
    }
    __syncthreads();

    // ---- Phase 3: mean-sim dots + zero masked rows + per-warp early store ----
    {
        const float4* sv = (const float4*)sm->s_s;
        const float4 s0 = sv[lane], s1 = sv[32 + lane];
        const float4 z  = make_float4(0.f, 0.f, 0.f, 0.f);
        float dms[4];
        #pragma unroll
        for (int i = 0; i < 4; i++) {
            const int r = rbase + 1 + i;
            const float4 lo = t4[r * 64 + lane];
            const float4 hi = t4[r * 64 + 32 + lane];
            dms[i] = dot4(lo, s0) + dot4(hi, s1);
        }
        #pragma unroll
        for (int o = 16; o; o >>= 1) {
            #pragma unroll
            for (int i = 0; i < 4; i++) dms[i] += __shfl_xor_sync(0xFFFFFFFFu, dms[i], o);
        }
        #pragma unroll
        for (int i = 0; i < 4; i++) {
            const int r = rbase + 1 + i;
            const bool m3 = ((t0 + 4 * warp + i) == 0) ||
                            (sm->inv_s[r] * sm->inv_s[r - 1] * da[i] < 0.7f);
            if (!m3) { t4[r * 64 + lane] = z;  t4[r * 64 + 32 + lane] = z; }
        }
        if (lane == 0) {
            #pragma unroll
            for (int i = 0; i < 4; i++)
                sm->ms_s[4 * warp + i] = sm->inv_s[rbase + 1 + i] * dms[i] * (1.0f / 32.0f);
        }
        // this warp's 4 rows are final -> 4 KB bulk store now
        __syncwarp();
        if (lane == 0) {
            asm volatile("fence.proxy.async.shared::cta;" ::: "memory");
            asm volatile("cp.async.bulk.global.shared::cta.bulk_group.L2::cache_hint"
                         " [%0], [%1], %2, %3;"
                         :: "l"(comp_out + (size_t)(t0 + 4 * warp) * 256),
                            "r"(smem_u32(sm->tile) + (uint32_t)(rbase + 1) * 1024u),
                            "r"(4096u), "l"(pol) : "memory");
            asm volatile("cp.async.bulk.commit_group;" ::: "memory");
        }
    }
    __syncthreads();

    // ---- Phase 4: window statistics (warp 0) ----
    if (warp == 0) {
        const float m = sm->ms_s[lane];
        float mu = warp_sum(m) * (1.0f / 32.0f);
        float d = m - mu;
        float var = warp_sum(d * d) * (1.0f / 31.0f);   // ddof=1
        float sd = sqrtf(var);
        bool keep = !(m > mu + sd);
        unsigned bal = __ballot_sync(0xFFFFFFFFu, keep);
        if (bal == 0u) {
            // fallback: keep argmin(mean_sim), first index on ties
            float bv = m; int bi = lane;
            #pragma unroll
            for (int o = 16; o; o >>= 1) {
                float ov = __shfl_xor_sync(0xFFFFFFFFu, bv, o);
                int   oi = __shfl_xor_sync(0xFFFFFFFFu, bi, o);
                if (ov < bv || (ov == bv && oi < bi)) { bv = ov; bi = oi; }
            }
            keep = (lane == bi);
        }
        mask_out[t0 + lane] = keep ? 1.0f : 0.0f;
    }

    // smem-reuse safety only: wait until the bulk unit has READ our smem.
    // (Write-to-global completion is guaranteed at the kernel boundary.)
    if (lane == 0) {
        asm volatile("cp.async.bulk.wait_group.read 0;" ::: "memory");
    }
}

extern "C" void kernel_launch(void* const* d_in, const int* in_sizes, int n_in,
                              void* d_out, int out_size)
{
    const float* x = (const float*)d_in[0];
    const int N = in_sizes[0] / 256;       // tokens
    const int nwin = N / WTOK;             // windows

    float* out = (float*)d_out;
    float* mask_out = out;                 // first N floats
    float* comp_out = out + N;             // N*256 floats

    cudaFuncSetAttribute(focus_kernel,
                         cudaFuncAttributeMaxDynamicSharedMemorySize,
                         (int)sizeof(Smem));
    focus_kernel<<<nwin, 256, sizeof(Smem)>>>(x, mask_out, comp_out);
}

// round 13
// speedup vs baseline: 1.0228x; 1.0019x over previous
#include <cuda_runtime.h>
#include <cstdint>

// FocusModules, one-shot TMA per window, 256-thread CTAs, 6 CTAs/SM.
// x: [N, 256] f32.  out (float32): [ mask1 (N) | compressed (N*256) ].
//
// One CTA per 32-token window (8192 CTAs). Tile rows 0..32 = tokens t0-1..t0+31.
// mean_sim[i] = inv_i * dot(raw_i, s)/32, s[c] = sum_r raw[r][c]*inv_r.
// Rolling pass fuses norms + adjacent dots; per-warp early TMA stores.
// L2 evict_first on both streams; split-arrive final barrier lets warps 1-7
// retire while warp 0 computes window statistics.

#define WTOK 32

struct __align__(128) Smem {
    float tile[33 * 256];        // 33 KB
    float s_s[256];              // weighted column sums
    float inv_s[33];             // per-row 1/||x||
    float ms_s[WTOK];            // per-token mean similarity
    unsigned long long mbar;
};

__device__ __forceinline__ uint32_t smem_u32(const void* p) {
    return (uint32_t)__cvta_generic_to_shared(p);
}
__device__ __forceinline__ float warp_sum(float v) {
    #pragma unroll
    for (int o = 16; o; o >>= 1) v += __shfl_xor_sync(0xFFFFFFFFu, v, o);
    return v;
}
__device__ __forceinline__ float dot4(float4 a, float4 b) {
    return a.x * b.x + a.y * b.y + a.z * b.z + a.w * b.w;
}

__global__ void __launch_bounds__(256, 6)
focus_kernel(const float* __restrict__ x,
             float* __restrict__ mask_out,        // N floats (0/1)
             float* __restrict__ comp_out)        // N*256 floats
{
    extern __shared__ __align__(128) char smem_raw[];
    Smem* sm = reinterpret_cast<Smem*>(smem_raw);

    const int w     = blockIdx.x;
    const int warp  = threadIdx.x >> 5;   // 0..7, owns tokens 4w..4w+3
    const int lane  = threadIdx.x & 31;
    const int t0    = w * WTOK;
    const int rbase = 4 * warp;           // warp reads rows rbase..rbase+4

    uint64_t pol;                         // streaming: evict_first in L2
    asm volatile("createpolicy.fractional.L2::evict_first.b64 %0;" : "=l"(pol));

    // ---- Bulk load rows t0-1 .. t0+31 (w=0: rows t0..t0+31 into tile+1KB) ----
    const uint32_t mb = smem_u32(&sm->mbar);
    if (threadIdx.x == 0) {
        asm volatile("mbarrier.init.shared::cta.b64 [%0], %1;" :: "r"(mb), "r"(1) : "memory");
        asm volatile("fence.proxy.async.shared::cta;" ::: "memory");
        const uint32_t bytes = (w ? 33u : 32u) * 1024u;
        const float*   src   = x + (size_t)(w ? (t0 - 1) : 0) * 256;
        const uint32_t dst   = smem_u32(sm->tile) + (w ? 0u : 1024u);
        asm volatile("mbarrier.arrive.expect_tx.shared::cta.b64 _, [%0], %1;"
                     :: "r"(mb), "r"(bytes) : "memory");
        asm volatile("cp.async.bulk.shared::cta.global.mbarrier::complete_tx::bytes.L2::cache_hint"
                     " [%0], [%1], %2, [%3], %4;"
                     :: "r"(dst), "l"(src), "r"(bytes), "r"(mb), "l"(pol) : "memory");
    }
    __syncthreads();
    asm volatile(
        "{\n\t.reg .pred P;\n\t"
        "W%=:\n\t"
        "mbarrier.try_wait.parity.acquire.cta.shared::cta.b64 P, [%0], 0;\n\t"
        "@P bra D%=;\n\t"
        "bra W%=;\n\t"
        "D%=:\n\t}"
        :: "r"(mb) : "memory");

    float4* t4 = (float4*)sm->tile;
    if (w == 0 && warp == 0) {           // deterministic row 0 for window 0
        const float4 z = make_float4(0.f, 0.f, 0.f, 0.f);
        t4[lane] = z;  t4[32 + lane] = z;
        __syncwarp();                    // warp 0 reads row 0 right below
    }

    // ---- Phase 1: one rolling pass -> norms (5 rows) + adjacent raw dots (4) ----
    float da[4];
    {
        float nrm[5];
        float4 plo, phi;
        #pragma unroll
        for (int i = 0; i < 5; i++) {
            const float4 lo = t4[(rbase + i) * 64 + lane];
            const float4 hi = t4[(rbase + i) * 64 + 32 + lane];
            nrm[i] = dot4(lo, lo) + dot4(hi, hi);
            if (i > 0) da[i - 1] = dot4(lo, plo) + dot4(hi, phi);
            plo = lo;  phi = hi;
        }
        #pragma unroll
        for (int o = 16; o; o >>= 1) {
            #pragma unroll
            for (int i = 0; i < 5; i++) nrm[i] += __shfl_xor_sync(0xFFFFFFFFu, nrm[i], o);
            #pragma unroll
            for (int i = 0; i < 4; i++) da[i]  += __shfl_xor_sync(0xFFFFFFFFu, da[i],  o);
        }
        if (lane == 0) {
            #pragma unroll
            for (int i = 1; i < 5; i++)
                sm->inv_s[rbase + i] = 1.0f / fmaxf(sqrtf(nrm[i]), 1e-12f);
            if (warp == 0)
                sm->inv_s[0] = 1.0f / fmaxf(sqrtf(nrm[0]), 1e-12f);
        }
    }
    __syncthreads();

    // ---- Phase 2: weighted column sums (deterministic order) ----
    {
        const int c = threadIdx.x;        // 256 threads, one column each
        float acc = 0.0f;
        #pragma unroll
        for (int r = 1; r <= WTOK; r++) acc += sm->tile[r * 256 + c] * sm->inv_s[r];
        sm->s_s[c] = acc;
    }
    __syncthreads();

    // ---- Phase 3: mean-sim dots + zero masked rows + per-warp early store ----
    {
        const float4* sv = (const float4*)sm->s_s;
        const float4 s0 = sv[lane], s1 = sv[32 + lane];
        const float4 z  = make_float4(0.f, 0.f, 0.f, 0.f);
        float dms[4];
        #pragma unroll
        for (int i = 0; i < 4; i++) {
            const int r = rbase + 1 + i;
            const float4 lo = t4[r * 64 + lane];
            const float4 hi = t4[r * 64 + 32 + lane];
            dms[i] = dot4(lo, s0) + dot4(hi, s1);
        }
        #pragma unroll
        for (int o = 16; o; o >>= 1) {
            #pragma unroll
            for (int i = 0; i < 4; i++) dms[i] += __shfl_xor_sync(0xFFFFFFFFu, dms[i], o);
        }
        #pragma unroll
        for (int i = 0; i < 4; i++) {
            const int r = rbase + 1 + i;
            const bool m3 = ((t0 + 4 * warp + i) == 0) ||
                            (sm->inv_s[r] * sm->inv_s[r - 1] * da[i] < 0.7f);
            if (!m3) { t4[r * 64 + lane] = z;  t4[r * 64 + 32 + lane] = z; }
        }
        if (lane == 0) {
            #pragma unroll
            for (int i = 0; i < 4; i++)
                sm->ms_s[4 * warp + i] = sm->inv_s[rbase + 1 + i] * dms[i] * (1.0f / 32.0f);
        }
        // this warp's 4 rows are final -> 4 KB bulk store now
        __syncwarp();
        if (lane == 0) {
            asm volatile("fence.proxy.async.shared::cta;" ::: "memory");
            asm volatile("cp.async.bulk.global.shared::cta.bulk_group.L2::cache_hint"
                         " [%0], [%1], %2, %3;"
                         :: "l"(comp_out + (size_t)(t0 + 4 * warp) * 256),
                            "r"(smem_u32(sm->tile) + (uint32_t)(rbase + 1) * 1024u),
                            "r"(4096u), "l"(pol) : "memory");
            asm volatile("cp.async.bulk.commit_group;" ::: "memory");
        }
    }

    // ---- Phase 4: split-arrive barrier; only warp 0 blocks for statistics ----
    if (warp != 0) {
        asm volatile("bar.arrive 1, 256;" ::: "memory");
        // smem-reuse safety: the bulk unit must have READ our smem before retire.
        if (lane == 0) {
            asm volatile("cp.async.bulk.wait_group.read 0;" ::: "memory");
        }
        return;
    }
    asm volatile("bar.sync 1, 256;" ::: "memory");
    {
        const float m = sm->ms_s[lane];
        float mu = warp_sum(m) * (1.0f / 32.0f);
        float d = m - mu;
        float var = warp_sum(d * d) * (1.0f / 31.0f);   // ddof=1
        float sd = sqrtf(var);
        bool keep = !(m > mu + sd);
        unsigned bal = __ballot_sync(0xFFFFFFFFu, keep);
        if (bal == 0u) {
            // fallback: keep argmin(mean_sim), first index on ties
            float bv = m; int bi = lane;
            #pragma unroll
            for (int o = 16; o; o >>= 1) {
                float ov = __shfl_xor_sync(0xFFFFFFFFu, bv, o);
                int   oi = __shfl_xor_sync(0xFFFFFFFFu, bi, o);
                if (ov < bv || (ov == bv && oi < bi)) { bv = ov; bi = oi; }
            }
            keep = (lane == bi);
        }
        __stcs(mask_out + t0 + lane, keep ? 1.0f : 0.0f);
    }
    if (lane == 0) {
        asm volatile("cp.async.bulk.wait_group.read 0;" ::: "memory");
    }
}

extern "C" void kernel_launch(void* const* d_in, const int* in_sizes, int n_in,
                              void* d_out, int out_size)
{
    const float* x = (const float*)d_in[0];
    const int N = in_sizes[0] / 256;       // tokens
    const int nwin = N / WTOK;             // windows

    float* out = (float*)d_out;
    float* mask_out = out;                 // first N floats
    float* comp_out = out + N;             // N*256 floats

    cudaFuncSetAttribute(focus_kernel,
                         cudaFuncAttributeMaxDynamicSharedMemorySize,
                         (int)sizeof(Smem));
    focus_kernel<<<nwin, 256, sizeof(Smem)>>>(x, mask_out, comp_out);
}